// round 3
// baseline (speedup 1.0000x reference)
#include <cuda_runtime.h>

// GraphPyramidPooling — adjacency (d_in[0]) is dead code for the output.
// Live path: per-level sigmoid scores -> exact stable top-k rank -> gather/
// gate/scatter. Levels: 4096 -> 3276 -> 1965 -> 786.
//
// R2: rank kernel is register-tiled (R=4 i's per thread -> 16 compares per
// LDS.128, breaking the LSU-issue bottleneck) and uses a uniform strict-gt
// comparator with per-i bit-decremented thresholds:
//   s_j >= s_i  <=>  s_j > prev_float(s_i)   (positive floats, monotone bits)
// so ALL chunks run the same branch-free loop; the single chunk straddling i
// gets an exact scalar equality correction.

#define D   512
#define DV  (D/4)
#define N0  4096
#define K0  3276
#define N1  3276
#define K1  1965
#define N2  1965
#define K2  786

__device__ float g_s0[N0];
__device__ float g_s1[N1];
__device__ float g_s2[N2];
__device__ int   g_r0[N0];
__device__ int   g_r1[N1];
__device__ int   g_r2[N2];
__device__ float g_h1[(size_t)N1 * D];
__device__ float g_h2[(size_t)N2 * D];

__device__ __forceinline__ float warp_sum(float v) {
#pragma unroll
    for (int o = 16; o; o >>= 1) v += __shfl_xor_sync(0xffffffffu, v, o);
    return v;
}
__device__ __forceinline__ float sigmoidf(float x) {
    return 1.0f / (1.0f + expf(-x));
}

// Level-0 scores: one warp per row. Also zeroes g_r0.
__global__ void scores0_kernel(const float* __restrict__ h,
                               const float* __restrict__ W,
                               const float* __restrict__ b) {
    int w    = (blockIdx.x * blockDim.x + threadIdx.x) >> 5;
    int lane = threadIdx.x & 31;
    if (w >= N0) return;
    const float4* hr = (const float4*)h + (size_t)w * DV;
    const float4* w0 = (const float4*)W;
    float acc = 0.f;
#pragma unroll
    for (int i = 0; i < 4; i++) {
        float4 a = __ldg(hr + lane + 32 * i);
        float4 c = __ldg(w0 + lane + 32 * i);
        acc += a.x * c.x + a.y * c.y + a.z * c.z + a.w * c.w;
    }
    acc = warp_sum(acc);
    if (lane == 0) {
        g_s0[w] = sigmoidf(acc + __ldg(b + 0));
        g_r0[w] = 0;
    }
}

// Exact stable-descending rank via register-tiled counting.
// rank(i) = #{j : s_j > s_i} + #{j < i : s_j == s_i}
// Per-thread threshold: thr = prev_float(s_i) when chunk start <= i (chunk is
// below-or-straddling i: ">=" semantics), thr = s_i when chunk entirely above
// (">" semantics). The straddling chunk over-counts equals at j >= i; the
// scalar correction subtracts them (including the j == i self-hit).
template <int LVL, int R, int CH, int TPB>
__global__ void rank_kernel() {
    const float* s = (LVL == 0) ? g_s0 : (LVL == 1) ? g_s1 : g_s2;
    int*         r = (LVL == 0) ? g_r0 : (LVL == 1) ? g_r1 : g_r2;
    const int    n = (LVL == 0) ? N0   : (LVL == 1) ? N1   : N2;

    __shared__ float sm[CH];
    const int c0 = blockIdx.y * CH;
    const int nc = min(CH, n - c0);
    const int i0 = blockIdx.x * (R * TPB);

    for (int t = threadIdx.x; t < nc; t += TPB) sm[t] = s[c0 + t];
    __syncthreads();

    float thr[R];
    int   cnt[R];
#pragma unroll
    for (int rr = 0; rr < R; rr++) {
        int i = i0 + rr * TPB + threadIdx.x;
        float si = (i < n) ? __ldg(s + i) : 2.0f;  // 2.0 > all sigmoids
        // chunk start <= i  -> use ">=" semantics (bit-decrement threshold)
        thr[rr] = (c0 <= i) ? __int_as_float(__float_as_int(si) - 1) : si;
        cnt[rr] = 0;
    }

    const float4* sm4 = (const float4*)sm;
    const int nc4 = nc >> 2;
#pragma unroll 4
    for (int q = 0; q < nc4; q++) {
        float4 v = sm4[q];
#pragma unroll
        for (int rr = 0; rr < R; rr++) {
            cnt[rr] += (v.x > thr[rr]) + (v.y > thr[rr]) +
                       (v.z > thr[rr]) + (v.w > thr[rr]);
        }
    }
    for (int j = nc4 * 4; j < nc; j++) {
        float v = sm[j];
#pragma unroll
        for (int rr = 0; rr < R; rr++) cnt[rr] += (v > thr[rr]);
    }

#pragma unroll
    for (int rr = 0; rr < R; rr++) {
        int i = i0 + rr * TPB + threadIdx.x;
        if (i >= n) continue;
        if (c0 <= i && i < c0 + nc) {
            // straddling chunk: remove equals at j >= i (self included)
            float si = __int_as_float(__float_as_int(thr[rr]) + 1);
            for (int j = i - c0; j < nc; j++) cnt[rr] -= (sm[j] == si);
        }
        if (cnt[rr]) atomicAdd(r + i, cnt[rr]);
    }
}

// Level-0 build: out[r] = selected ? h[r]*s : 0 (covers poison), scatter to
// h1[rank], fused next-level matvec for s1. Zeroes g_r1 slots it owns.
__global__ void build0_kernel(const float* __restrict__ h,
                              const float* __restrict__ W,
                              const float* __restrict__ b,
                              float* __restrict__ out) {
    int w    = (blockIdx.x * blockDim.x + threadIdx.x) >> 5;
    int lane = threadIdx.x & 31;
    if (w >= N0) return;
    int rank = g_r0[w];
    const float4* hr   = (const float4*)h + (size_t)w * DV;
    float4*       outr = (float4*)out + (size_t)w * DV;
    if (rank < K0) {
        float val = g_s0[w];
        float4*       h1r = (float4*)g_h1 + (size_t)rank * DV;
        const float4* w1  = (const float4*)W + DV;
        float acc = 0.f;
#pragma unroll
        for (int i = 0; i < 4; i++) {
            float4 a = __ldg(hr + lane + 32 * i);
            a.x *= val; a.y *= val; a.z *= val; a.w *= val;
            outr[lane + 32 * i] = a;
            h1r[lane + 32 * i]  = a;
            float4 c = __ldg(w1 + lane + 32 * i);
            acc += a.x * c.x + a.y * c.y + a.z * c.z + a.w * c.w;
        }
        acc = warp_sum(acc);
        if (lane == 0) {
            g_s1[rank] = sigmoidf(acc + __ldg(b + 1));
            g_r1[rank] = 0;
        }
    } else {
        float4 z = make_float4(0.f, 0.f, 0.f, 0.f);
#pragma unroll
        for (int i = 0; i < 4; i++) outr[lane + 32 * i] = z;
    }
}

// Level-1 build: out[p] += h1[p]*s1[p], scatter h2[rank], fused s2 matvec.
__global__ void build1_kernel(const float* __restrict__ W,
                              const float* __restrict__ b,
                              float* __restrict__ out) {
    int w    = (blockIdx.x * blockDim.x + threadIdx.x) >> 5;
    int lane = threadIdx.x & 31;
    if (w >= N1) return;
    int rank = g_r1[w];
    if (rank >= K1) return;
    float val = g_s1[w];
    const float4* h1r  = (const float4*)g_h1 + (size_t)w * DV;
    float4*       outr = (float4*)out + (size_t)w * DV;
    float4*       h2r  = (float4*)g_h2 + (size_t)rank * DV;
    const float4* w2   = (const float4*)W + 2 * DV;
    float acc = 0.f;
#pragma unroll
    for (int i = 0; i < 4; i++) {
        float4 a = h1r[lane + 32 * i];
        a.x *= val; a.y *= val; a.z *= val; a.w *= val;
        float4 o = outr[lane + 32 * i];
        o.x += a.x; o.y += a.y; o.z += a.z; o.w += a.w;
        outr[lane + 32 * i] = o;
        h2r[lane + 32 * i]  = a;
        float4 c = __ldg(w2 + lane + 32 * i);
        acc += a.x * c.x + a.y * c.y + a.z * c.z + a.w * c.w;
    }
    acc = warp_sum(acc);
    if (lane == 0) {
        g_s2[rank] = sigmoidf(acc + __ldg(b + 2));
        g_r2[rank] = 0;
    }
}

// Level-2 build: out[p] += h2[p]*s2[p] for selected p.
__global__ void build2_kernel(float* __restrict__ out) {
    int w    = (blockIdx.x * blockDim.x + threadIdx.x) >> 5;
    int lane = threadIdx.x & 31;
    if (w >= N2) return;
    int rank = g_r2[w];
    if (rank >= K2) return;
    float val = g_s2[w];
    const float4* h2r  = (const float4*)g_h2 + (size_t)w * DV;
    float4*       outr = (float4*)out + (size_t)w * DV;
#pragma unroll
    for (int i = 0; i < 4; i++) {
        float4 a = h2r[lane + 32 * i];
        float4 o = outr[lane + 32 * i];
        o.x += a.x * val; o.y += a.y * val; o.z += a.z * val; o.w += a.w * val;
        outr[lane + 32 * i] = o;
    }
}

extern "C" void kernel_launch(void* const* d_in, const int* in_sizes, int n_in,
                              void* d_out, int out_size) {
    // inputs: [0]=g (UNUSED), [1]=h [4096,512], [2]=W [3,512], [3]=b [3]
    const float* h = (const float*)d_in[1];
    const float* W = (const float*)d_in[2];
    const float* b = (const float*)d_in[3];
    float* out = (float*)d_out;

    scores0_kernel<<<N0 / 8, 256>>>(h, W, b);

    // rank0: tiles of 512 i's (128 thr x R4), CH=64 -> 8 x 64 = 512 blocks
    rank_kernel<0, 4, 64, 128><<<dim3(8, 64), 128>>>();
    build0_kernel<<<N0 / 8, 256>>>(h, W, b, out);

    // rank1: 7 x 52 = 364 blocks (tile 512, CH=64)
    rank_kernel<1, 4, 64, 128><<<dim3((N1 + 511) / 512, (N1 + 63) / 64), 128>>>();
    build1_kernel<<<(N1 * 32 + 255) / 256, 256>>>(W, b, out);

    // rank2: 4 x 62 = 248 blocks (tile 512, CH=32)
    rank_kernel<2, 4, 32, 128><<<dim3((N2 + 511) / 512, (N2 + 31) / 32), 128>>>();
    build2_kernel<<<(N2 * 32 + 255) / 256, 256>>>(out);
}